// round 7
// baseline (speedup 1.0000x reference)
#include <cuda_runtime.h>
#include <math.h>

typedef unsigned long long ull;

// Problem dims
#define NN 512
#define TT 64
#define CC 64
#define HH 4
#define HD 16
#define MM (NN*TT)      // 32768 rows
#define EPS 1e-5f

// ---------------------------------------------------------------------------
// Scratch
// ---------------------------------------------------------------------------
#define SZ 2097152
#define OFF_QH   0
#define OFF_KH   (1*SZ)
#define OFF_VH   (2*SZ)
#define OFF_ATT  (3*SZ)
#define OFF_X    (4*SZ)
#define OFF_H    (5*SZ)     // size 4*SZ: attention partials, later FFN hidden
#define OFF_OUT1 (9*SZ)
#define OFF_T1   (10*SZ)
#define OFF_T2   (11*SZ)
#define OFF_T3   (12*SZ)
#define OFF_OUT2 (13*SZ)
#define OFF_ZA   (14*SZ)    // attention pl partials early, gating za later
#define OFF_PART (15*SZ)
#define OFF_STAT (15*SZ + 1024)
#define SCRATCH_TOTAL (15*SZ + 1024 + 16)

__device__ __align__(16) float g_scratch[SCRATCH_TOTAL];

// ---------------------------------------------------------------------------
// Packed f32x2 helpers (Blackwell native FFMA2)
// ---------------------------------------------------------------------------
__device__ __forceinline__ ull pk2(float x, float y) {
    ull r; asm("mov.b64 %0, {%1, %2};" : "=l"(r) : "f"(x), "f"(y)); return r;
}
__device__ __forceinline__ void upk2(ull v, float& x, float& y) {
    asm("mov.b64 {%0, %1}, %2;" : "=f"(x), "=f"(y) : "l"(v));
}
__device__ __forceinline__ ull ffma2(ull a, ull b, ull c) {
    ull d; asm("fma.rn.f32x2 %0, %1, %2, %3;" : "=l"(d) : "l"(a), "l"(b), "l"(c)); return d;
}

// ---------------------------------------------------------------------------
// adj InstanceNorm stats
// ---------------------------------------------------------------------------
__global__ void adj_rowred_kernel(const float* __restrict__ adj, float* __restrict__ part) {
    __shared__ float s1[256], s2[256];
    int r = blockIdx.x, t = threadIdx.x;
    float a = adj[r * 512 + t];
    float b = adj[r * 512 + 256 + t];
    s1[t] = a + b;
    s2[t] = a * a + b * b;
    __syncthreads();
    for (int st = 128; st > 0; st >>= 1) {
        if (t < st) { s1[t] += s1[t + st]; s2[t] += s2[t + st]; }
        __syncthreads();
    }
    if (t == 0) { part[r] = s1[0]; part[512 + r] = s2[0]; }
}

__global__ void adj_final_kernel(const float* __restrict__ part, float* __restrict__ stats) {
    __shared__ float s1[256], s2[256];
    int t = threadIdx.x;
    s1[t] = part[t] + part[t + 256];
    s2[t] = part[512 + t] + part[512 + t + 256];
    __syncthreads();
    for (int st = 128; st > 0; st >>= 1) {
        if (t < st) { s1[t] += s1[t + st]; s2[t] += s2[t + st]; }
        __syncthreads();
    }
    if (t == 0) {
        float mean = s1[0] * (1.0f / 262144.0f);
        float var  = s2[0] * (1.0f / 262144.0f) - mean * mean;
        stats[0] = mean;
        stats[1] = rsqrtf(var + EPS);
    }
}

// ---------------------------------------------------------------------------
// Per-head projections q/k/v -> [T,H,N,HD]
// ---------------------------------------------------------------------------
__global__ void proj_kernel(const float* __restrict__ q, const float* __restrict__ k,
                            const float* __restrict__ v,
                            const float* __restrict__ Wq, const float* __restrict__ Wk,
                            const float* __restrict__ Wv,
                            float* __restrict__ qh, float* __restrict__ kh,
                            float* __restrict__ vh) {
    __shared__ float wq[16][17], wk[16][17], wv[16][17];
    __shared__ float rq[4][64], rk[4][64], rv[4][64];
    int tid = threadIdx.x;
    {
        int d = tid >> 4, e = tid & 15;
        wq[e][d] = Wq[tid];
        wk[e][d] = Wk[tid];
        wv[e][d] = Wv[tid];
    }
    int g = tid >> 6, c = tid & 63;
    int row = blockIdx.x * 4 + g;
    rq[g][c] = q[row * 64 + c];
    rk[g][c] = k[row * 64 + c];
    rv[g][c] = v[row * 64 + c];
    __syncthreads();
    int hh = c >> 4, d = c & 15;
    float sq = 0.f, sk = 0.f, sv = 0.f;
#pragma unroll
    for (int e = 0; e < 16; e++) {
        sq += rq[g][hh * 16 + e] * wq[e][d];
        sk += rk[g][hh * 16 + e] * wk[e][d];
        sv += rv[g][hh * 16 + e] * wv[e][d];
    }
    int n = row / TT, t = row % TT;
    int o = ((t * HH + hh) * NN + n) * HD + d;
    qh[o] = sq; kh[o] = sk; vh[o] = sv;
}

// ---------------------------------------------------------------------------
// Node-attention partials, packed f32x2.
// grid (256, 2, 4): x=(t,h), y=row-half (256 q rows), z=k-chunk (128 keys).
// 128 threads, 2 q-rows per thread. K/V chunk [128,16] in smem (16KB).
// No running max needed (scores tiny); partials directly additive.
// ---------------------------------------------------------------------------
__global__ void __launch_bounds__(128) attn_part_kernel(
        const float* __restrict__ qh, const float* __restrict__ kh,
        const float* __restrict__ vh,
        float* __restrict__ pacc, float* __restrict__ pl) {
    __shared__ float Ks[128 * HD];
    __shared__ float Vs[128 * HD];
    int th = blockIdx.x;
    int rh = blockIdx.y;
    int ck = blockIdx.z;
    size_t base = (size_t)th * (NN * HD);
    size_t cbase = base + (size_t)ck * (128 * HD);
    {
        const float4* k4 = reinterpret_cast<const float4*>(kh + cbase);
        const float4* v4 = reinterpret_cast<const float4*>(vh + cbase);
        float4* ks4 = reinterpret_cast<float4*>(Ks);
        float4* vs4 = reinterpret_cast<float4*>(Vs);
#pragma unroll
        for (int i = 0; i < 4; i++) {
            int idx = threadIdx.x + i * 128;
            ks4[idx] = k4[idx];
            vs4[idx] = v4[idx];
        }
    }
    __syncthreads();

    const float SCL = 0.125f * 1.44269504088896f;  // 1/sqrt(C) * log2(e)
    int q0 = rh * 256 + threadIdx.x * 2;
    ull qp0[8], qp1[8];
#pragma unroll
    for (int i = 0; i < 4; i++) {
        float4 a = reinterpret_cast<const float4*>(qh + base + (size_t)q0 * HD)[i];
        float4 b = reinterpret_cast<const float4*>(qh + base + (size_t)(q0 + 1) * HD)[i];
        qp0[i * 2 + 0] = pk2(a.x * SCL, a.y * SCL);
        qp0[i * 2 + 1] = pk2(a.z * SCL, a.w * SCL);
        qp1[i * 2 + 0] = pk2(b.x * SCL, b.y * SCL);
        qp1[i * 2 + 1] = pk2(b.z * SCL, b.w * SCL);
    }

    ull ac0[8], ac1[8];
    ull z = pk2(0.f, 0.f);
#pragma unroll
    for (int d = 0; d < 8; d++) { ac0[d] = z; ac1[d] = z; }
    float l0 = 0.f, l1 = 0.f;

    for (int k = 0; k < 128; k++) {
        ull kr[8];
        {
            const ulonglong2* kp = reinterpret_cast<const ulonglong2*>(Ks + k * HD);
#pragma unroll
            for (int i = 0; i < 4; i++) {
                ulonglong2 t2 = kp[i];
                kr[i * 2] = t2.x; kr[i * 2 + 1] = t2.y;
            }
        }
        // two independent 4-deep chains per row
        ull s0a = z, s0b = z, s1a = z, s1b = z;
#pragma unroll
        for (int d = 0; d < 4; d++) {
            s0a = ffma2(qp0[d], kr[d], s0a);
            s0b = ffma2(qp0[d + 4], kr[d + 4], s0b);
            s1a = ffma2(qp1[d], kr[d], s1a);
            s1b = ffma2(qp1[d + 4], kr[d + 4], s1b);
        }
        float ax, ay, bx, by, cx, cy, dx, dy;
        upk2(s0a, ax, ay); upk2(s0b, bx, by);
        upk2(s1a, cx, cy); upk2(s1b, dx, dy);
        float p0 = exp2f((ax + ay) + (bx + by));
        float p1 = exp2f((cx + cy) + (dx + dy));
        l0 += p0; l1 += p1;
        ull pp0 = pk2(p0, p0), pp1 = pk2(p1, p1);
        {
            const ulonglong2* vp = reinterpret_cast<const ulonglong2*>(Vs + k * HD);
#pragma unroll
            for (int i = 0; i < 4; i++) {
                ulonglong2 t2 = vp[i];
                ac0[i * 2]     = ffma2(pp0, t2.x, ac0[i * 2]);
                ac0[i * 2 + 1] = ffma2(pp0, t2.y, ac0[i * 2 + 1]);
                ac1[i * 2]     = ffma2(pp1, t2.x, ac1[i * 2]);
                ac1[i * 2 + 1] = ffma2(pp1, t2.y, ac1[i * 2 + 1]);
            }
        }
    }

    // store partials (unnormalized)
    size_t pbase0 = ((size_t)(ck * 256 + th) * 512 + q0) * HD;
    size_t pbase1 = pbase0 + HD;
#pragma unroll
    for (int i = 0; i < 4; i++) {
        float x0, y0, x1, y1;
        float4 o;
        upk2(ac0[i * 2], x0, y0); upk2(ac0[i * 2 + 1], x1, y1);
        o.x = x0; o.y = y0; o.z = x1; o.w = y1;
        reinterpret_cast<float4*>(pacc + pbase0)[i] = o;
        upk2(ac1[i * 2], x0, y0); upk2(ac1[i * 2 + 1], x1, y1);
        o.x = x0; o.y = y0; o.z = x1; o.w = y1;
        reinterpret_cast<float4*>(pacc + pbase1)[i] = o;
    }
    pl[(size_t)ck * 131072 + th * 512 + q0]     = l0;
    pl[(size_t)ck * 131072 + th * 512 + q0 + 1] = l1;
}

// Combine the 4 k-chunks, normalize, write to [N,T,C] layout.
__global__ void attn_combine_kernel(const float* __restrict__ pacc,
                                    const float* __restrict__ pl,
                                    float* __restrict__ attn) {
    int th = blockIdx.x;
    int t = th >> 2, h = th & 3;
#pragma unroll
    for (int j = 0; j < 2; j++) {
        int q = threadIdx.x * 2 + j;
        float l = 0.f;
#pragma unroll
        for (int c = 0; c < 4; c++) l += pl[(size_t)c * 131072 + th * 512 + q];
        float inv = 1.f / l;
        float* o = attn + ((size_t)q * TT + t) * CC + h * HD;
#pragma unroll
        for (int i = 0; i < 4; i++) {
            float4 s = {0.f, 0.f, 0.f, 0.f};
#pragma unroll
            for (int c = 0; c < 4; c++) {
                size_t ib = ((size_t)(c * 256 + th) * 512 + q) * HD;
                float4 a = reinterpret_cast<const float4*>(pacc + ib)[i];
                s.x += a.x; s.y += a.y; s.z += a.z; s.w += a.w;
            }
            s.x *= inv; s.y *= inv; s.z *= inv; s.w *= inv;
            reinterpret_cast<float4*>(o)[i] = s;
        }
    }
}

// ---------------------------------------------------------------------------
// fp32 packed-f32x2 GEMM, 128x64 tile, BK=32, 256 threads.
// Thread microtile: 4 rows (ty+32i) x 8 cols (8tx..8tx+7).
// A staged PRE-DUPLICATED as packed ull (LDS.64 broadcast pair directly).
// B staged k-major floats, read as 2x LDS.128 per k.
//   Y[M,N] = A[M,K] @ op(B)
//   BROW=true : B is [K,N] row-major (GCN spatial)
//   BROW=false: B is W[N,K] row-major, op = transpose (nn.Linear)
//   ANORM: normalize A on load: (a - stats[0]) * stats[1]
//   EPI: 0=none, 1=bias+relu, 2=bias,
//        3=bias+residual(R)+LayerNorm(P1=gamma,P2=beta)  [N==64, grid.x==1]
//        4=gate: zb=acc+bias; g=sigmoid(R+zb); Y=g*P1+(1-g)*P2  [N==64]
// ---------------------------------------------------------------------------
#define LDA_U 33      // ull stride for Asd rows
#define LDB_F 72      // float stride for Bs rows
#define LDO_F 68      // float stride for output tile

template<int EPI, bool BROW, bool ANORM, int BMOD>
__global__ void __launch_bounds__(256) gemm128(
        const float* __restrict__ A, const float* __restrict__ B,
        const float* __restrict__ bias, const float* __restrict__ R,
        const float* __restrict__ P1, const float* __restrict__ P2,
        const float* __restrict__ stats,
        float* __restrict__ Y, int M, int N, int K) {
    __shared__ __align__(16) char smbuf[128 * LDA_U * 8 + 32 * LDB_F * 4];
    ull*   Asd = reinterpret_cast<ull*>(smbuf);
    float* Bs  = reinterpret_cast<float*>(smbuf + 128 * LDA_U * 8);

    int tid = threadIdx.x;
    int tx = tid & 7, ty = tid >> 3;          // tx: 8 col-groups, ty: 32 row-groups
    int rowBase = blockIdx.y * 128, colBase = blockIdx.x * 64;

    float s0 = 0.f, s1 = 1.f;
    if (ANORM) { s0 = stats[0]; s1 = stats[1]; }

    ull acc2[4][4];
    ull z = pk2(0.f, 0.f);
#pragma unroll
    for (int i = 0; i < 4; i++)
#pragma unroll
        for (int j = 0; j < 4; j++) acc2[i][j] = z;

    for (int k0 = 0; k0 < K; k0 += 32) {
        // stage A [128 x 32] duplicated into packed ulls
#pragma unroll
        for (int it = 0; it < 4; it++) {
            int idx = tid + it * 256;
            int m = idx >> 3;
            int kq = (idx & 7) * 4;
            float4 v = *reinterpret_cast<const float4*>(&A[(size_t)(rowBase + m) * K + k0 + kq]);
            if (ANORM) {
                v.x = (v.x - s0) * s1; v.y = (v.y - s0) * s1;
                v.z = (v.z - s0) * s1; v.w = (v.w - s0) * s1;
            }
            ull* dst = &Asd[m * LDA_U + kq];
            dst[0] = pk2(v.x, v.x);
            dst[1] = pk2(v.y, v.y);
            dst[2] = pk2(v.z, v.z);
            dst[3] = pk2(v.w, v.w);
        }
        // stage B k-major: Bs[kk][col]
        if (BROW) {
#pragma unroll
            for (int it = 0; it < 2; it++) {
                int idx = tid + it * 256;
                int kk = idx >> 4;
                int j = (idx & 15) * 4;
                float4 v = *reinterpret_cast<const float4*>(&B[(size_t)(k0 + kk) * N + colBase + j]);
                *reinterpret_cast<float4*>(&Bs[kk * LDB_F + j]) = v;
            }
        } else {
            // transpose-stage W[N,K]: Bs[kk][n] = W[colBase+n][k0+kk]
#pragma unroll
            for (int it = 0; it < 2; it++) {
                int idx = tid + it * 256;
                int n = idx >> 3;
                int kq = (idx & 7) * 4;
                float4 v = *reinterpret_cast<const float4*>(&B[(size_t)(colBase + n) * K + k0 + kq]);
                Bs[(kq + 0) * LDB_F + n] = v.x;
                Bs[(kq + 1) * LDB_F + n] = v.y;
                Bs[(kq + 2) * LDB_F + n] = v.z;
                Bs[(kq + 3) * LDB_F + n] = v.w;
            }
        }
        __syncthreads();

#pragma unroll 8
        for (int e = 0; e < 32; e++) {
            ulonglong2 bp0 = *reinterpret_cast<const ulonglong2*>(&Bs[e * LDB_F + 8 * tx]);
            ulonglong2 bp1 = *reinterpret_cast<const ulonglong2*>(&Bs[e * LDB_F + 8 * tx + 4]);
#pragma unroll
            for (int i = 0; i < 4; i++) {
                ull a2 = Asd[(ty + 32 * i) * LDA_U + e];
                acc2[i][0] = ffma2(a2, bp0.x, acc2[i][0]);
                acc2[i][1] = ffma2(a2, bp0.y, acc2[i][1]);
                acc2[i][2] = ffma2(a2, bp1.x, acc2[i][2]);
                acc2[i][3] = ffma2(a2, bp1.y, acc2[i][3]);
            }
        }
        __syncthreads();
    }

    // unpack accumulators: v[i][0..7] = cols 8tx..8tx+7 of row ty+32i
    float v[4][8];
#pragma unroll
    for (int i = 0; i < 4; i++)
#pragma unroll
        for (int j = 0; j < 4; j++) upk2(acc2[i][j], v[i][2 * j], v[i][2 * j + 1]);

    if (EPI == 3) {
        // bias + residual into smem tile, then LayerNorm over 64 cols
        float* sO = reinterpret_cast<float*>(smbuf);
        int col0 = 8 * tx;
        float4 b0 = *reinterpret_cast<const float4*>(&bias[col0]);
        float4 b1 = *reinterpret_cast<const float4*>(&bias[col0 + 4]);
#pragma unroll
        for (int i = 0; i < 4; i++) {
            int rr = ty + 32 * i;
            const float* Rr = &R[(size_t)(rowBase + rr) * 64 + col0];
            float4 r0 = *reinterpret_cast<const float4*>(Rr);
            float4 r1 = *reinterpret_cast<const float4*>(Rr + 4);
            float4 o0, o1;
            o0.x = v[i][0] + b0.x + r0.x; o0.y = v[i][1] + b0.y + r0.y;
            o0.z = v[i][2] + b0.z + r0.z; o0.w = v[i][3] + b0.w + r0.w;
            o1.x = v[i][4] + b1.x + r1.x; o1.y = v[i][5] + b1.y + r1.y;
            o1.z = v[i][6] + b1.z + r1.z; o1.w = v[i][7] + b1.w + r1.w;
            *reinterpret_cast<float4*>(&sO[rr * LDO_F + col0]) = o0;
            *reinterpret_cast<float4*>(&sO[rr * LDO_F + col0 + 4]) = o1;
        }
        __syncthreads();
        int row = tid >> 1;
        int half = (tid & 1) * 32;
        float sum = 0.f, sq = 0.f;
#pragma unroll
        for (int c = 0; c < 32; c++) {
            float x = sO[row * LDO_F + half + c];
            sum += x; sq += x * x;
        }
        sum += __shfl_xor_sync(0xffffffff, sum, 1);
        sq  += __shfl_xor_sync(0xffffffff, sq, 1);
        float mean = sum * (1.f / 64.f);
        float var = sq * (1.f / 64.f) - mean * mean;
        float rs = rsqrtf(var + EPS);
#pragma unroll
        for (int c4 = 0; c4 < 8; c4++) {
            int c = half + c4 * 4;
            float4 a = *reinterpret_cast<const float4*>(&sO[row * LDO_F + c]);
            float4 g = *reinterpret_cast<const float4*>(&P1[c]);
            float4 bb = *reinterpret_cast<const float4*>(&P2[c]);
            float4 o;
            o.x = (a.x - mean) * rs * g.x + bb.x;
            o.y = (a.y - mean) * rs * g.y + bb.y;
            o.z = (a.z - mean) * rs * g.z + bb.z;
            o.w = (a.w - mean) * rs * g.w + bb.w;
            *reinterpret_cast<float4*>(&Y[(size_t)(rowBase + row) * 64 + c]) = o;
        }
    } else {
        int col0 = colBase + 8 * tx;
#pragma unroll
        for (int i = 0; i < 4; i++) {
            int r = rowBase + ty + 32 * i;
            float o[8];
#pragma unroll
            for (int j = 0; j < 8; j++) o[j] = v[i][j];
            if (EPI == 1 || EPI == 2 || EPI == 4) {
#pragma unroll
                for (int j = 0; j < 8; j++) o[j] += bias[(col0 + j) & (BMOD - 1)];
            }
            if (EPI == 1) {
#pragma unroll
                for (int j = 0; j < 8; j++) o[j] = fmaxf(o[j], 0.f);
            }
            if (EPI == 4) {
                const float* Rr = &R[(size_t)r * N + col0];
                const float* p1 = &P1[(size_t)r * N + col0];
                const float* p2 = &P2[(size_t)r * N + col0];
#pragma unroll
                for (int j = 0; j < 8; j++) {
                    float s = 1.f / (1.f + __expf(-(Rr[j] + o[j])));
                    o[j] = s * p1[j] + (1.f - s) * p2[j];
                }
            }
            float4 o0 = {o[0], o[1], o[2], o[3]};
            float4 o1 = {o[4], o[5], o[6], o[7]};
            *reinterpret_cast<float4*>(&Y[(size_t)r * N + col0]) = o0;
            *reinterpret_cast<float4*>(&Y[(size_t)r * N + col0 + 4]) = o1;
        }
    }
}

// ---------------------------------------------------------------------------
extern "C" void kernel_launch(void* const* d_in, const int* in_sizes, int n_in,
                              void* d_out, int out_size) {
    const float* value = (const float*)d_in[0];
    const float* key_t = (const float*)d_in[1];
    const float* query = (const float*)d_in[2];
    const float* adj   = (const float*)d_in[3];
    const float* Wv    = (const float*)d_in[4];
    const float* Wk    = (const float*)d_in[5];
    const float* Wq    = (const float*)d_in[6];
    const float* Wo    = (const float*)d_in[7];
    const float* bo    = (const float*)d_in[8];
    const float* g1    = (const float*)d_in[9];
    const float* b1    = (const float*)d_in[10];
    const float* g2    = (const float*)d_in[11];
    const float* b2    = (const float*)d_in[12];
    const float* Wf1   = (const float*)d_in[13];
    const float* bf1   = (const float*)d_in[14];
    const float* Wf2   = (const float*)d_in[15];
    const float* bf2   = (const float*)d_in[16];
    const float* Wg1   = (const float*)d_in[17];
    const float* bg1   = (const float*)d_in[18];
    const float* Wg2   = (const float*)d_in[19];
    const float* bg2   = (const float*)d_in[20];
    const float* Wo1   = (const float*)d_in[21];
    const float* bo1   = (const float*)d_in[22];
    const float* Wo2   = (const float*)d_in[23];
    const float* bo2   = (const float*)d_in[24];
    float* out = (float*)d_out;

    float* base;
    cudaGetSymbolAddress((void**)&base, g_scratch);
    float* qh    = base + OFF_QH;
    float* kh    = base + OFF_KH;
    float* vh    = base + OFF_VH;
    float* attnb = base + OFF_ATT;
    float* x     = base + OFF_X;
    float* hbuf  = base + OFF_H;    // FFN hidden (after attention done)
    float* pacc  = base + OFF_H;    // attention partials: 4*256*512*16 = 8.4M floats
    float* pl    = base + OFF_ZA;   // 4*131072 floats (za reused later)
    float* out1  = base + OFF_OUT1;
    float* t1    = base + OFF_T1;
    float* t2    = base + OFF_T2;
    float* t3    = base + OFF_T3;
    float* out2  = base + OFF_OUT2;
    float* za    = base + OFF_ZA;
    float* part  = base + OFF_PART;
    float* stat  = base + OFF_STAT;

    // adj InstanceNorm stats
    adj_rowred_kernel<<<512, 256>>>(adj, part);
    adj_final_kernel<<<1, 256>>>(part, stat);

    // head projections
    proj_kernel<<<MM / 4, 256>>>(query, key_t, value, Wq, Wk, Wv, qh, kh, vh);

    // node-attention: split-K=4 partials + combine
    attn_part_kernel<<<dim3(TT * HH, 2, 4), 128>>>(qh, kh, vh, pacc, pl);
    attn_combine_kernel<<<TT * HH, 256>>>(pacc, pl, attnb);

    // z1 = attn@Wo^T + bo + query; x = LN1(z1)
    gemm128<3, false, false, 64><<<dim3(1, MM / 128), 256>>>(
        attnb, Wo, bo, query, g1, b1, nullptr, x, MM, 64, 64);

    // FFN: hbuf = relu(x@Wf1^T + bf1); out1 = LN2(hbuf@Wf2^T + bf2 + x)
    gemm128<1, false, false, 256><<<dim3(4, MM / 128), 256>>>(
        x, Wf1, bf1, nullptr, nullptr, nullptr, nullptr, hbuf, MM, 256, 64);
    gemm128<3, false, false, 64><<<dim3(1, MM / 128), 256>>>(
        hbuf, Wf2, bf2, x, g2, b2, nullptr, out1, MM, 64, 256);

    // GCN: t1 = query@Wg1^T; t2 = relu(adjn@t1 + bg1); t3 = t2@Wg2^T; out2 = adjn@t3 + bg2
    gemm128<0, false, false, 64><<<dim3(1, MM / 128), 256>>>(
        query, Wg1, nullptr, nullptr, nullptr, nullptr, nullptr, t1, MM, 64, 64);
    gemm128<1, true, true, 64><<<dim3(64, 4), 256>>>(
        adj, t1, bg1, nullptr, nullptr, nullptr, stat, t2, 512, 4096, 512);
    gemm128<0, false, false, 64><<<dim3(1, MM / 128), 256>>>(
        t2, Wg2, nullptr, nullptr, nullptr, nullptr, nullptr, t3, MM, 64, 64);
    gemm128<2, true, true, 64><<<dim3(64, 4), 256>>>(
        adj, t3, bg2, nullptr, nullptr, nullptr, stat, out2, 512, 4096, 512);

    // gating: za = out1@Wo1^T + bo1; out = sig(za + out2@Wo2^T + bo2)*out1 + (1-sig)*out2
    gemm128<2, false, false, 64><<<dim3(1, MM / 128), 256>>>(
        out1, Wo1, bo1, nullptr, nullptr, nullptr, nullptr, za, MM, 64, 64);
    gemm128<4, false, false, 64><<<dim3(1, MM / 128), 256>>>(
        out2, Wo2, bo2, za, out1, out2, nullptr, out, MM, 64, 64);
}

// round 8
// speedup vs baseline: 1.1386x; 1.1386x over previous
#include <cuda_runtime.h>
#include <math.h>

typedef unsigned long long ull;

// Problem dims
#define NN 512
#define TT 64
#define CC 64
#define HH 4
#define HD 16
#define MM (NN*TT)      // 32768 rows
#define EPS 1e-5f

// ---------------------------------------------------------------------------
// Scratch
// ---------------------------------------------------------------------------
#define SZ 2097152
#define OFF_QH   0
#define OFF_KH   (1*SZ)
#define OFF_VH   (2*SZ)
#define OFF_ATT  (3*SZ)
#define OFF_X    (4*SZ)
#define OFF_H    (5*SZ)     // size 4*SZ: attention partials, later FFN hidden
#define OFF_OUT1 (9*SZ)
#define OFF_T1   (10*SZ)
#define OFF_T2   (11*SZ)
#define OFF_T3   (12*SZ)
#define OFF_OUT2 (13*SZ)
#define OFF_ZA   (14*SZ)    // attention pl partials early, gating za later
#define OFF_PART (15*SZ)
#define OFF_STAT (15*SZ + 1024)
#define SCRATCH_TOTAL (15*SZ + 1024 + 16)

__device__ __align__(16) float g_scratch[SCRATCH_TOTAL];

// ---------------------------------------------------------------------------
// Packed f32x2 helpers (Blackwell native FFMA2)
// ---------------------------------------------------------------------------
__device__ __forceinline__ ull pk2(float x, float y) {
    ull r; asm("mov.b64 %0, {%1, %2};" : "=l"(r) : "f"(x), "f"(y)); return r;
}
__device__ __forceinline__ void upk2(ull v, float& x, float& y) {
    asm("mov.b64 {%0, %1}, %2;" : "=f"(x), "=f"(y) : "l"(v));
}
__device__ __forceinline__ ull ffma2(ull a, ull b, ull c) {
    ull d; asm("fma.rn.f32x2 %0, %1, %2, %3;" : "=l"(d) : "l"(a), "l"(b), "l"(c)); return d;
}

// ---------------------------------------------------------------------------
// adj InstanceNorm stats
// ---------------------------------------------------------------------------
__global__ void adj_rowred_kernel(const float* __restrict__ adj, float* __restrict__ part) {
    __shared__ float s1[256], s2[256];
    int r = blockIdx.x, t = threadIdx.x;
    float a = adj[r * 512 + t];
    float b = adj[r * 512 + 256 + t];
    s1[t] = a + b;
    s2[t] = a * a + b * b;
    __syncthreads();
    for (int st = 128; st > 0; st >>= 1) {
        if (t < st) { s1[t] += s1[t + st]; s2[t] += s2[t + st]; }
        __syncthreads();
    }
    if (t == 0) { part[r] = s1[0]; part[512 + r] = s2[0]; }
}

__global__ void adj_final_kernel(const float* __restrict__ part, float* __restrict__ stats) {
    __shared__ float s1[256], s2[256];
    int t = threadIdx.x;
    s1[t] = part[t] + part[t + 256];
    s2[t] = part[512 + t] + part[512 + t + 256];
    __syncthreads();
    for (int st = 128; st > 0; st >>= 1) {
        if (t < st) { s1[t] += s1[t + st]; s2[t] += s2[t + st]; }
        __syncthreads();
    }
    if (t == 0) {
        float mean = s1[0] * (1.0f / 262144.0f);
        float var  = s2[0] * (1.0f / 262144.0f) - mean * mean;
        stats[0] = mean;
        stats[1] = rsqrtf(var + EPS);
    }
}

// ---------------------------------------------------------------------------
// Per-head projections q/k/v -> [T,H,N,HD]
// ---------------------------------------------------------------------------
__global__ void proj_kernel(const float* __restrict__ q, const float* __restrict__ k,
                            const float* __restrict__ v,
                            const float* __restrict__ Wq, const float* __restrict__ Wk,
                            const float* __restrict__ Wv,
                            float* __restrict__ qh, float* __restrict__ kh,
                            float* __restrict__ vh) {
    __shared__ float wq[16][17], wk[16][17], wv[16][17];
    __shared__ float rq[4][64], rk[4][64], rv[4][64];
    int tid = threadIdx.x;
    {
        int d = tid >> 4, e = tid & 15;
        wq[e][d] = Wq[tid];
        wk[e][d] = Wk[tid];
        wv[e][d] = Wv[tid];
    }
    int g = tid >> 6, c = tid & 63;
    int row = blockIdx.x * 4 + g;
    rq[g][c] = q[row * 64 + c];
    rk[g][c] = k[row * 64 + c];
    rv[g][c] = v[row * 64 + c];
    __syncthreads();
    int hh = c >> 4, d = c & 15;
    float sq = 0.f, sk = 0.f, sv = 0.f;
#pragma unroll
    for (int e = 0; e < 16; e++) {
        sq += rq[g][hh * 16 + e] * wq[e][d];
        sk += rk[g][hh * 16 + e] * wk[e][d];
        sv += rv[g][hh * 16 + e] * wv[e][d];
    }
    int n = row / TT, t = row % TT;
    int o = ((t * HH + hh) * NN + n) * HD + d;
    qh[o] = sq; kh[o] = sk; vh[o] = sv;
}

// ---------------------------------------------------------------------------
// Node-attention partials, packed f32x2, 4 q-rows per thread.
// grid (256, 4): x=(t,h), y=k-chunk (128 keys). 128 threads.
// K/V chunk [128,16] in smem (16KB). K/V smem loads amortize over 4 rows.
// No running max (scores tiny); partials directly additive.
// ---------------------------------------------------------------------------
__global__ void __launch_bounds__(128) attn_part_kernel(
        const float* __restrict__ qh, const float* __restrict__ kh,
        const float* __restrict__ vh,
        float* __restrict__ pacc, float* __restrict__ pl) {
    __shared__ float Ks[128 * HD];
    __shared__ float Vs[128 * HD];
    int th = blockIdx.x;
    int ck = blockIdx.y;
    size_t base = (size_t)th * (NN * HD);
    size_t cbase = base + (size_t)ck * (128 * HD);
    {
        const float4* k4 = reinterpret_cast<const float4*>(kh + cbase);
        const float4* v4 = reinterpret_cast<const float4*>(vh + cbase);
        float4* ks4 = reinterpret_cast<float4*>(Ks);
        float4* vs4 = reinterpret_cast<float4*>(Vs);
#pragma unroll
        for (int i = 0; i < 4; i++) {
            int idx = threadIdx.x + i * 128;
            ks4[idx] = k4[idx];
            vs4[idx] = v4[idx];
        }
    }
    __syncthreads();

    const float SCL = 0.125f * 1.44269504088896f;  // 1/sqrt(C) * log2(e)
    int q0 = threadIdx.x * 4;
    ull qp[4][8];
#pragma unroll
    for (int r = 0; r < 4; r++) {
#pragma unroll
        for (int i = 0; i < 4; i++) {
            float4 a = reinterpret_cast<const float4*>(qh + base + (size_t)(q0 + r) * HD)[i];
            qp[r][i * 2 + 0] = pk2(a.x * SCL, a.y * SCL);
            qp[r][i * 2 + 1] = pk2(a.z * SCL, a.w * SCL);
        }
    }

    ull ac[4][8];
    ull z = pk2(0.f, 0.f);
#pragma unroll
    for (int r = 0; r < 4; r++)
#pragma unroll
        for (int d = 0; d < 8; d++) ac[r][d] = z;
    float l[4] = {0.f, 0.f, 0.f, 0.f};

    for (int k = 0; k < 128; k++) {
        ull kr[8];
        {
            const ulonglong2* kp = reinterpret_cast<const ulonglong2*>(Ks + k * HD);
#pragma unroll
            for (int i = 0; i < 4; i++) {
                ulonglong2 t2 = kp[i];
                kr[i * 2] = t2.x; kr[i * 2 + 1] = t2.y;
            }
        }
        float p[4];
#pragma unroll
        for (int r = 0; r < 4; r++) {
            ull sa = z, sb = z;
#pragma unroll
            for (int d = 0; d < 4; d++) {
                sa = ffma2(qp[r][d], kr[d], sa);
                sb = ffma2(qp[r][d + 4], kr[d + 4], sb);
            }
            float ax, ay, bx, by;
            upk2(sa, ax, ay); upk2(sb, bx, by);
            p[r] = exp2f((ax + ay) + (bx + by));
            l[r] += p[r];
        }
        ull pp[4];
#pragma unroll
        for (int r = 0; r < 4; r++) pp[r] = pk2(p[r], p[r]);
        {
            const ulonglong2* vp = reinterpret_cast<const ulonglong2*>(Vs + k * HD);
#pragma unroll
            for (int i = 0; i < 4; i++) {
                ulonglong2 t2 = vp[i];
#pragma unroll
                for (int r = 0; r < 4; r++) {
                    ac[r][i * 2]     = ffma2(pp[r], t2.x, ac[r][i * 2]);
                    ac[r][i * 2 + 1] = ffma2(pp[r], t2.y, ac[r][i * 2 + 1]);
                }
            }
        }
    }

    // store partials (unnormalized)
#pragma unroll
    for (int r = 0; r < 4; r++) {
        size_t pbase = ((size_t)(ck * 256 + th) * 512 + q0 + r) * HD;
#pragma unroll
        for (int i = 0; i < 4; i++) {
            float x0, y0, x1, y1;
            upk2(ac[r][i * 2], x0, y0); upk2(ac[r][i * 2 + 1], x1, y1);
            float4 o = {x0, y0, x1, y1};
            reinterpret_cast<float4*>(pacc + pbase)[i] = o;
        }
        pl[(size_t)ck * 131072 + th * 512 + q0 + r] = l[r];
    }
}

// Combine the 4 k-chunks, normalize, write to [N,T,C] layout.
__global__ void attn_combine_kernel(const float* __restrict__ pacc,
                                    const float* __restrict__ pl,
                                    float* __restrict__ attn) {
    int th = blockIdx.x;
    int t = th >> 2, h = th & 3;
#pragma unroll
    for (int j = 0; j < 2; j++) {
        int q = threadIdx.x * 2 + j;
        float l = 0.f;
#pragma unroll
        for (int c = 0; c < 4; c++) l += pl[(size_t)c * 131072 + th * 512 + q];
        float inv = 1.f / l;
        float* o = attn + ((size_t)q * TT + t) * CC + h * HD;
#pragma unroll
        for (int i = 0; i < 4; i++) {
            float4 s = {0.f, 0.f, 0.f, 0.f};
#pragma unroll
            for (int c = 0; c < 4; c++) {
                size_t ib = ((size_t)(c * 256 + th) * 512 + q) * HD;
                float4 a = reinterpret_cast<const float4*>(pacc + ib)[i];
                s.x += a.x; s.y += a.y; s.z += a.z; s.w += a.w;
            }
            s.x *= inv; s.y *= inv; s.z *= inv; s.w *= inv;
            reinterpret_cast<float4*>(o)[i] = s;
        }
    }
}

// ---------------------------------------------------------------------------
// fp32 packed-f32x2 GEMM, 64x64 tile, BK=64, 256 threads (R6 shape).
// A staged PRE-DUPLICATED as packed ull via STS.128 pairs: inner loop has no
// pk2 MOVs. B staged k-major; cols read as one LDS.128 (ulonglong2).
// Unpadded strides (broadcast A reads; B LDS.128 phases conflict-free).
// Static smem = 32KB (A) + 16KB (B) = 48KB exactly.
//   Y[M,N] = A[M,K] @ op(B)
//   BROW=true : B is [K,N] row-major (GCN spatial)
//   BROW=false: B is W[N,K] row-major, op = transpose (nn.Linear)
//   ANORM: normalize A on load: (a - stats[0]) * stats[1]
//   EPI: 0=none, 1=bias+relu, 2=bias,
//        3=bias+residual(R)+LayerNorm(P1=gamma,P2=beta)  [N==64, grid.x==1]
//        4=gate: zb=acc+bias; g=sigmoid(R+zb); Y=g*P1+(1-g)*P2  [N==64]
// ---------------------------------------------------------------------------
template<int EPI, bool BROW, bool ANORM, int BMOD>
__global__ void __launch_bounds__(256) gemm64(
        const float* __restrict__ A, const float* __restrict__ B,
        const float* __restrict__ bias, const float* __restrict__ R,
        const float* __restrict__ P1, const float* __restrict__ P2,
        const float* __restrict__ stats,
        float* __restrict__ Y, int M, int N, int K) {
    __shared__ __align__(16) char smbuf[64 * 64 * 8 + 64 * 64 * 4];
    ull*   Asd = reinterpret_cast<ull*>(smbuf);                    // [64][64] ull
    float* Bs  = reinterpret_cast<float*>(smbuf + 64 * 64 * 8);    // [64][64] float

    int tid = threadIdx.x;
    int tx = tid & 15, ty = tid >> 4;
    int rowBase = blockIdx.y * 64, colBase = blockIdx.x * 64;

    float s0 = 0.f, s1 = 1.f;
    if (ANORM) { s0 = stats[0]; s1 = stats[1]; }

    ull acc2[4][2];
    ull z = pk2(0.f, 0.f);
#pragma unroll
    for (int i = 0; i < 4; i++) { acc2[i][0] = z; acc2[i][1] = z; }

    for (int k0 = 0; k0 < K; k0 += 64) {
        // stage A [64 x 64] duplicated into packed ulls (2x STS.128 per float4)
#pragma unroll
        for (int it = 0; it < 4; it++) {
            int idx = tid + it * 256;
            int m = idx >> 4;
            int kq = (idx & 15) * 4;
            float4 v = *reinterpret_cast<const float4*>(&A[(size_t)(rowBase + m) * K + k0 + kq]);
            if (ANORM) {
                v.x = (v.x - s0) * s1; v.y = (v.y - s0) * s1;
                v.z = (v.z - s0) * s1; v.w = (v.w - s0) * s1;
            }
            ulonglong2 d0, d1;
            d0.x = pk2(v.x, v.x); d0.y = pk2(v.y, v.y);
            d1.x = pk2(v.z, v.z); d1.y = pk2(v.w, v.w);
            *reinterpret_cast<ulonglong2*>(&Asd[m * 64 + kq]) = d0;
            *reinterpret_cast<ulonglong2*>(&Asd[m * 64 + kq + 2]) = d1;
        }
        // stage B k-major: Bs[kk][col]
        if (BROW) {
#pragma unroll
            for (int it = 0; it < 4; it++) {
                int idx = tid + it * 256;
                int kk = idx >> 4;
                int j = (idx & 15) * 4;
                float4 v = *reinterpret_cast<const float4*>(&B[(size_t)(k0 + kk) * N + colBase + j]);
                *reinterpret_cast<float4*>(&Bs[kk * 64 + j]) = v;
            }
        } else {
            // transpose-stage W[N,K]: Bs[kk][n] = W[colBase+n][k0+kk]
#pragma unroll
            for (int it = 0; it < 4; it++) {
                int idx = tid + it * 256;
                int n = idx & 63;
                int kq = (idx >> 6) * 4;
                float4 v = *reinterpret_cast<const float4*>(&B[(size_t)(colBase + n) * K + k0 + kq]);
                Bs[(kq + 0) * 64 + n] = v.x;
                Bs[(kq + 1) * 64 + n] = v.y;
                Bs[(kq + 2) * 64 + n] = v.z;
                Bs[(kq + 3) * 64 + n] = v.w;
            }
        }
        __syncthreads();

#pragma unroll 8
        for (int e = 0; e < 64; e++) {
            ulonglong2 bp = *reinterpret_cast<const ulonglong2*>(&Bs[e * 64 + 4 * tx]);
#pragma unroll
            for (int i = 0; i < 4; i++) {
                ull a2 = Asd[(ty + 16 * i) * 64 + e];
                acc2[i][0] = ffma2(a2, bp.x, acc2[i][0]);
                acc2[i][1] = ffma2(a2, bp.y, acc2[i][1]);
            }
        }
        __syncthreads();
    }

    // unpack accumulators
    float v[4][4];
#pragma unroll
    for (int i = 0; i < 4; i++) {
        upk2(acc2[i][0], v[i][0], v[i][1]);
        upk2(acc2[i][1], v[i][2], v[i][3]);
    }

    if (EPI == 3) {
        // bias + residual into smem tile [64][64], then LayerNorm over 64 cols
        float* sO = reinterpret_cast<float*>(smbuf);
#pragma unroll
        for (int i = 0; i < 4; i++) {
            int rr = ty + 16 * i;
            float4 rz = *reinterpret_cast<const float4*>(&R[(size_t)(rowBase + rr) * 64 + 4 * tx]);
            float4 o;
            o.x = v[i][0] + bias[4 * tx + 0] + rz.x;
            o.y = v[i][1] + bias[4 * tx + 1] + rz.y;
            o.z = v[i][2] + bias[4 * tx + 2] + rz.z;
            o.w = v[i][3] + bias[4 * tx + 3] + rz.w;
            *reinterpret_cast<float4*>(&sO[rr * 64 + 4 * tx]) = o;
        }
        __syncthreads();
        int row = tid >> 2;
        int qq = (tid & 3) * 16;
        float sum = 0.f, sq = 0.f;
#pragma unroll
        for (int c = 0; c < 16; c++) {
            float x = sO[row * 64 + qq + c];
            sum += x; sq += x * x;
        }
        sum += __shfl_xor_sync(0xffffffff, sum, 1);
        sum += __shfl_xor_sync(0xffffffff, sum, 2);
        sq  += __shfl_xor_sync(0xffffffff, sq, 1);
        sq  += __shfl_xor_sync(0xffffffff, sq, 2);
        float mean = sum * (1.f / 64.f);
        float var = sq * (1.f / 64.f) - mean * mean;
        float rs = rsqrtf(var + EPS);
#pragma unroll
        for (int c4 = 0; c4 < 4; c4++) {
            int c = qq + c4 * 4;
            float4 a = *reinterpret_cast<const float4*>(&sO[row * 64 + c]);
            float4 g = *reinterpret_cast<const float4*>(&P1[c]);
            float4 bb = *reinterpret_cast<const float4*>(&P2[c]);
            float4 o;
            o.x = (a.x - mean) * rs * g.x + bb.x;
            o.y = (a.y - mean) * rs * g.y + bb.y;
            o.z = (a.z - mean) * rs * g.z + bb.z;
            o.w = (a.w - mean) * rs * g.w + bb.w;
            *reinterpret_cast<float4*>(&Y[(size_t)(rowBase + row) * 64 + c]) = o;
        }
    } else {
#pragma unroll
        for (int i = 0; i < 4; i++) {
            int r = rowBase + ty + 16 * i;
            int col0 = colBase + 4 * tx;
            float4 o;
            o.x = v[i][0]; o.y = v[i][1]; o.z = v[i][2]; o.w = v[i][3];
            if (EPI == 1 || EPI == 2 || EPI == 4) {
                o.x += bias[(col0 + 0) & (BMOD - 1)];
                o.y += bias[(col0 + 1) & (BMOD - 1)];
                o.z += bias[(col0 + 2) & (BMOD - 1)];
                o.w += bias[(col0 + 3) & (BMOD - 1)];
            }
            if (EPI == 1) {
                o.x = fmaxf(o.x, 0.f); o.y = fmaxf(o.y, 0.f);
                o.z = fmaxf(o.z, 0.f); o.w = fmaxf(o.w, 0.f);
            }
            if (EPI == 4) {
                float4 rz = *reinterpret_cast<const float4*>(&R[(size_t)r * N + col0]);
                float4 p1 = *reinterpret_cast<const float4*>(&P1[(size_t)r * N + col0]);
                float4 p2 = *reinterpret_cast<const float4*>(&P2[(size_t)r * N + col0]);
                float s;
                s = 1.f / (1.f + __expf(-(rz.x + o.x))); o.x = s * p1.x + (1.f - s) * p2.x;
                s = 1.f / (1.f + __expf(-(rz.y + o.y))); o.y = s * p1.y + (1.f - s) * p2.y;
                s = 1.f / (1.f + __expf(-(rz.z + o.z))); o.z = s * p1.z + (1.f - s) * p2.z;
                s = 1.f / (1.f + __expf(-(rz.w + o.w))); o.w = s * p1.w + (1.f - s) * p2.w;
            }
            *reinterpret_cast<float4*>(&Y[(size_t)r * N + col0]) = o;
        }
    }
}

// ---------------------------------------------------------------------------
extern "C" void kernel_launch(void* const* d_in, const int* in_sizes, int n_in,
                              void* d_out, int out_size) {
    const float* value = (const float*)d_in[0];
    const float* key_t = (const float*)d_in[1];
    const float* query = (const float*)d_in[2];
    const float* adj   = (const float*)d_in[3];
    const float* Wv    = (const float*)d_in[4];
    const float* Wk    = (const float*)d_in[5];
    const float* Wq    = (const float*)d_in[6];
    const float* Wo    = (const float*)d_in[7];
    const float* bo    = (const float*)d_in[8];
    const float* g1    = (const float*)d_in[9];
    const float* b1    = (const float*)d_in[10];
    const float* g2    = (const float*)d_in[11];
    const float* b2    = (const float*)d_in[12];
    const float* Wf1   = (const float*)d_in[13];
    const float* bf1   = (const float*)d_in[14];
    const float* Wf2   = (const float*)d_in[15];
    const float* bf2   = (const float*)d_in[16];
    const float* Wg1   = (const float*)d_in[17];
    const float* bg1   = (const float*)d_in[18];
    const float* Wg2   = (const float*)d_in[19];
    const float* bg2   = (const float*)d_in[20];
    const float* Wo1   = (const float*)d_in[21];
    const float* bo1   = (const float*)d_in[22];
    const float* Wo2   = (const float*)d_in[23];
    const float* bo2   = (const float*)d_in[24];
    float* out = (float*)d_out;

    float* base;
    cudaGetSymbolAddress((void**)&base, g_scratch);
    float* qh    = base + OFF_QH;
    float* kh    = base + OFF_KH;
    float* vh    = base + OFF_VH;
    float* attnb = base + OFF_ATT;
    float* x     = base + OFF_X;
    float* hbuf  = base + OFF_H;    // FFN hidden (after attention done)
    float* pacc  = base + OFF_H;    // attention partials: 4*256*512*16 = 8.4M floats
    float* pl    = base + OFF_ZA;   // 4*131072 floats (za reused later)
    float* out1  = base + OFF_OUT1;
    float* t1    = base + OFF_T1;
    float* t2    = base + OFF_T2;
    float* t3    = base + OFF_T3;
    float* out2  = base + OFF_OUT2;
    float* za    = base + OFF_ZA;
    float* part  = base + OFF_PART;
    float* stat  = base + OFF_STAT;

    // adj InstanceNorm stats
    adj_rowred_kernel<<<512, 256>>>(adj, part);
    adj_final_kernel<<<1, 256>>>(part, stat);

    // head projections
    proj_kernel<<<MM / 4, 256>>>(query, key_t, value, Wq, Wk, Wv, qh, kh, vh);

    // node-attention: split-K=4 partials (4 q-rows/thread) + combine
    attn_part_kernel<<<dim3(TT * HH, 4), 128>>>(qh, kh, vh, pacc, pl);
    attn_combine_kernel<<<TT * HH, 256>>>(pacc, pl, attnb);

    // z1 = attn@Wo^T + bo + query; x = LN1(z1)
    gemm64<3, false, false, 64><<<dim3(1, MM / 64), 256>>>(
        attnb, Wo, bo, query, g1, b1, nullptr, x, MM, 64, 64);

    // FFN: hbuf = relu(x@Wf1^T + bf1); out1 = LN2(hbuf@Wf2^T + bf2 + x)
    gemm64<1, false, false, 256><<<dim3(4, MM / 64), 256>>>(
        x, Wf1, bf1, nullptr, nullptr, nullptr, nullptr, hbuf, MM, 256, 64);
    gemm64<3, false, false, 64><<<dim3(1, MM / 64), 256>>>(
        hbuf, Wf2, bf2, x, g2, b2, nullptr, out1, MM, 64, 256);

    // GCN: t1 = query@Wg1^T; t2 = relu(adjn@t1 + bg1); t3 = t2@Wg2^T; out2 = adjn@t3 + bg2
    gemm64<0, false, false, 64><<<dim3(1, MM / 64), 256>>>(
        query, Wg1, nullptr, nullptr, nullptr, nullptr, nullptr, t1, MM, 64, 64);
    gemm64<1, true, true, 64><<<dim3(64, 8), 256>>>(
        adj, t1, bg1, nullptr, nullptr, nullptr, stat, t2, 512, 4096, 512);
    gemm64<0, false, false, 64><<<dim3(1, MM / 64), 256>>>(
        t2, Wg2, nullptr, nullptr, nullptr, nullptr, nullptr, t3, MM, 64, 64);
    gemm64<2, true, true, 64><<<dim3(64, 8), 256>>>(
        adj, t3, bg2, nullptr, nullptr, nullptr, stat, out2, 512, 4096, 512);

    // gating: za = out1@Wo1^T + bo1; out = sig(za + out2@Wo2^T + bo2)*out1 + (1-sig)*out2
    gemm64<2, false, false, 64><<<dim3(1, MM / 64), 256>>>(
        out1, Wo1, bo1, nullptr, nullptr, nullptr, nullptr, za, MM, 64, 64);
    gemm64<4, false, false, 64><<<dim3(1, MM / 64), 256>>>(
        out2, Wo2, bo2, za, out1, out2, nullptr, out, MM, 64, 64);
}